// round 6
// baseline (speedup 1.0000x reference)
#include <cuda_runtime.h>
#include <cstdint>

// Problem constants
#define GM 9600          // B*Lq = 32*300
#define GK 256           // D_MODEL
#define NRAW 288         // 192 offset cols + 96 attn cols
#define BM 64
#define BN 96
#define BK 32

// Scratch for raw GEMM output (query @ [W_off | W_attn] + bias), ~11 MB.
__device__ float g_raw[GM * NRAW];

// ---------------------------------------------------------------------------
// Kernel 1: fused GEMM  raw[9600][288] = query @ [W_off(192) | W_attn(96)] + b
// Tiled fp32 SMEM GEMM. grid = (150, 3): y=0,1 -> W_off halves, y=2 -> W_attn.
// 256 threads as 16(m) x 16(n), micro-tile 4x6 per thread.
// ---------------------------------------------------------------------------
__global__ __launch_bounds__(256) void dfine_gemm_kernel(
    const float* __restrict__ A,      // query (9600 x 256)
    const float* __restrict__ Woff,   // (256 x 192)
    const float* __restrict__ boff,   // (192)
    const float* __restrict__ Wattn,  // (256 x 96)
    const float* __restrict__ battn)  // (96)
{
    // As padded to 68 floats/row: keeps 16B alignment for float4 LDS
    // (68*4=272 = 16*17) and breaks the 8-way STS bank conflict of stride 64.
    __shared__ float As[BK][68];
    __shared__ float Bs[BK][BN];

    const int tid  = threadIdx.x;
    const int rowBase = blockIdx.x * BM;
    const int nblk = blockIdx.y;

    const float* Bsrc;
    const float* bias;
    int ldB, colBase, nGlobalBase;
    if (nblk < 2) { Bsrc = Woff;  bias = boff;  ldB = 192; colBase = nblk * 96; nGlobalBase = nblk * 96; }
    else          { Bsrc = Wattn; bias = battn; ldB = 96;  colBase = 0;         nGlobalBase = 192; }

    const int ty = tid >> 4;   // 0..15 (m)
    const int tx = tid & 15;   // 0..15 (n)

    float acc[4][6];
    #pragma unroll
    for (int i = 0; i < 4; i++)
        #pragma unroll
        for (int j = 0; j < 6; j++) acc[i][j] = 0.0f;

    for (int k0 = 0; k0 < GK; k0 += BK) {
        // --- load A tile: 64 rows x 32 k = 512 float4, 2 per thread, transposed store
        #pragma unroll
        for (int i = 0; i < 2; i++) {
            int f  = tid + i * 256;       // float4 id 0..511
            int r  = f >> 3;              // row 0..63
            int kq = f & 7;               // k-quad 0..7
            float4 v = *reinterpret_cast<const float4*>(A + (rowBase + r) * GK + k0 + kq * 4);
            As[kq * 4 + 0][r] = v.x;
            As[kq * 4 + 1][r] = v.y;
            As[kq * 4 + 2][r] = v.z;
            As[kq * 4 + 3][r] = v.w;
        }
        // --- load B tile: 32 k x 96 n = 3072 floats, 12 per thread
        #pragma unroll
        for (int i = 0; i < 12; i++) {
            int e = tid + i * 256;
            int k = e / 96;
            int n = e - k * 96;
            Bs[k][n] = __ldg(Bsrc + (k0 + k) * ldB + colBase + n);
        }
        __syncthreads();

        #pragma unroll
        for (int k = 0; k < BK; k++) {
            float4 av = *reinterpret_cast<const float4*>(&As[k][ty * 4]);
            float a[4] = {av.x, av.y, av.z, av.w};
            float bv[6];
            // tx*6 floats = 24B offset: 8-byte aligned -> three float2 loads
            float2 b0 = *reinterpret_cast<const float2*>(&Bs[k][tx * 6 + 0]);
            float2 b1 = *reinterpret_cast<const float2*>(&Bs[k][tx * 6 + 2]);
            float2 b2 = *reinterpret_cast<const float2*>(&Bs[k][tx * 6 + 4]);
            bv[0] = b0.x; bv[1] = b0.y; bv[2] = b1.x; bv[3] = b1.y; bv[4] = b2.x; bv[5] = b2.y;
            #pragma unroll
            for (int i = 0; i < 4; i++)
                #pragma unroll
                for (int j = 0; j < 6; j++)
                    acc[i][j] = fmaf(a[i], bv[j], acc[i][j]);
        }
        __syncthreads();
    }

    // --- epilogue: add bias, write to g_raw
    #pragma unroll
    for (int i = 0; i < 4; i++) {
        int r = rowBase + ty * 4 + i;
        #pragma unroll
        for (int j = 0; j < 6; j++) {
            int n = tx * 6 + j;
            g_raw[r * NRAW + nGlobalBase + n] = acc[i][j] + __ldg(bias + colBase + n);
        }
    }
}

// ---------------------------------------------------------------------------
// Kernel 2: fused softmax + location transform + bilinear gather + weighted sum
// One block per (b, lq): 256 threads = 8 warps = 8 heads, lane = channel.
// ---------------------------------------------------------------------------
__global__ __launch_bounds__(256) void dfine_sample_kernel(
    const float* __restrict__ refp,   // (32,300,1,4)
    const float* __restrict__ value,  // input_flatten (32, 8400, 256)
    float* __restrict__ out)          // (32,300,256)
{
    __shared__ float sIx[96];
    __shared__ float sIy[96];
    __shared__ float sWt[96];
    __shared__ float sL[96];

    const int row = blockIdx.x;        // b*300 + lq
    const int b   = row / 300;
    const int tid = threadIdx.x;
    const float* raw = g_raw + (size_t)row * NRAW;

    if (tid < 96) {
        // head = tid/12, pt = tid%12; offset cols are interleaved (x,y)
        float rx = __ldg(refp + row * 4 + 0);
        float ry = __ldg(refp + row * 4 + 1);
        float rw = __ldg(refp + row * 4 + 2);
        float rh = __ldg(refp + row * 4 + 3);
        float ox = raw[2 * tid + 0];
        float oy = raw[2 * tid + 1];
        int pt  = tid % 12;
        int lvl = pt >> 2;
        float Wf = (lvl == 0) ? 80.0f : (lvl == 1) ? 40.0f : 20.0f;
        // pscale = 1/4 for all points; OFFSET_SCALE=0.5 -> 0.125
        float lx = rx + ox * 0.125f * rw;
        float ly = ry + oy * 0.125f * rh;
        // grid = 2*loc-1; pixel = ((g+1)*W-1)*0.5 = loc*W - 0.5
        sIx[tid] = lx * Wf - 0.5f;
        sIy[tid] = ly * Wf - 0.5f;
    } else if (tid < 192) {
        sL[tid - 96] = raw[192 + (tid - 96)];
    }
    __syncthreads();

    if (tid < 8) {
        // per-head softmax over 12 points
        float m = -1e30f;
        #pragma unroll
        for (int p = 0; p < 12; p++) m = fmaxf(m, sL[tid * 12 + p]);
        float e[12];
        float s = 0.0f;
        #pragma unroll
        for (int p = 0; p < 12; p++) { e[p] = expf(sL[tid * 12 + p] - m); s += e[p]; }
        float inv = 1.0f / s;
        #pragma unroll
        for (int p = 0; p < 12; p++) sWt[tid * 12 + p] = e[p] * inv;
    }
    __syncthreads();

    const int h    = tid >> 5;   // head = warp id
    const int lane = tid & 31;   // channel within head
    const float* vb = value + (size_t)b * 8400 * 256 + h * 32 + lane;

    float acc = 0.0f;
    #pragma unroll
    for (int pt = 0; pt < 12; pt++) {
        int lvl  = pt >> 2;
        int W    = (lvl == 0) ? 80 : (lvl == 1) ? 40 : 20;   // H == W
        int loff = (lvl == 0) ? 0  : (lvl == 1) ? 6400 : 8000;
        float ix = sIx[h * 12 + pt];
        float iy = sIy[h * 12 + pt];
        float wt = sWt[h * 12 + pt];

        float fx0 = floorf(ix), fy0 = floorf(iy);
        float fx = ix - fx0, fy = iy - fy0;
        int x0 = (int)fx0, y0 = (int)fy0;
        int x1 = x0 + 1,   y1 = y0 + 1;
        bool vx0 = (unsigned)x0 < (unsigned)W;
        bool vx1 = (unsigned)x1 < (unsigned)W;
        bool vy0 = (unsigned)y0 < (unsigned)W;
        bool vy1 = (unsigned)y1 < (unsigned)W;

        const float* base = vb + (size_t)loff * 256;
        float v00 = (vx0 && vy0) ? __ldg(base + (y0 * W + x0) * 256) : 0.0f;
        float v01 = (vx1 && vy0) ? __ldg(base + (y0 * W + x1) * 256) : 0.0f;
        float v10 = (vx0 && vy1) ? __ldg(base + (y1 * W + x0) * 256) : 0.0f;
        float v11 = (vx1 && vy1) ? __ldg(base + (y1 * W + x1) * 256) : 0.0f;

        float gx = 1.0f - fx, gy = 1.0f - fy;
        acc += wt * (gx * gy * v00 + fx * gy * v01 + gx * fy * v10 + fx * fy * v11);
    }

    out[(size_t)row * 256 + tid] = acc;
}

// ---------------------------------------------------------------------------
// Launch: inputs in metadata order:
//   0 query (32,300,256) f32        1 reference_points (32,300,1,4) f32
//   2 input_flatten (32,8400,256)   3 W_off (256,192)   4 b_off (192)
//   5 W_attn (256,96)               6 b_attn (96)
// Output: (32,300,256) f32
// ---------------------------------------------------------------------------
extern "C" void kernel_launch(void* const* d_in, const int* in_sizes, int n_in,
                              void* d_out, int out_size) {
    const float* query = (const float*)d_in[0];
    const float* refp  = (const float*)d_in[1];
    const float* value = (const float*)d_in[2];
    const float* Woff  = (const float*)d_in[3];
    const float* boff  = (const float*)d_in[4];
    const float* Wattn = (const float*)d_in[5];
    const float* battn = (const float*)d_in[6];
    float* out = (float*)d_out;

    dim3 ggrid(GM / BM, 3);  // 150 x 3
    dfine_gemm_kernel<<<ggrid, 256>>>(query, Woff, boff, Wattn, battn);
    dfine_sample_kernel<<<GM, 256>>>(refp, value, out);
}

// round 8
// speedup vs baseline: 1.9281x; 1.9281x over previous
#include <cuda_runtime.h>
#include <cstdint>

// Problem constants
#define GM 9600          // B*Lq = 32*300
#define GK 256           // D_MODEL
#define NRAW 288         // 192 offset cols + 96 attn cols
#define BM 64
#define BN 96
#define BK 32

// Scratch for raw GEMM output (query @ [W_off | W_attn] + bias), ~11 MB.
__device__ float g_raw[GM * NRAW];

// ---------------------------------------------------------------------------
// Kernel 1: fused GEMM  raw[9600][288] = query @ [W_off(192) | W_attn(96)] + b
// Double-buffered SMEM fp32 GEMM. grid = (150, 3): y=0,1 -> W_off halves,
// y=2 -> W_attn. 256 threads as 16(m) x 16(n), micro-tile 4x6 per thread.
// One __syncthreads per K-tile; next tile's LDGs issued before compute.
// ---------------------------------------------------------------------------
__global__ __launch_bounds__(256) void dfine_gemm_kernel(
    const float* __restrict__ A,      // query (9600 x 256)
    const float* __restrict__ Woff,   // (256 x 192)
    const float* __restrict__ boff,   // (192)
    const float* __restrict__ Wattn,  // (256 x 96)
    const float* __restrict__ battn)  // (96)
{
    // As padded to 68 floats/row: 16B alignment for float4 LDS and no
    // 8-way STS conflict.
    __shared__ float As[2][BK][68];
    __shared__ float Bs[2][BK][BN];

    const int tid  = threadIdx.x;
    const int rowBase = blockIdx.x * BM;
    const int nblk = blockIdx.y;

    const float* Bsrc;
    const float* bias;
    int ldB, colBase, nGlobalBase;
    if (nblk < 2) { Bsrc = Woff;  bias = boff;  ldB = 192; colBase = nblk * 96; nGlobalBase = nblk * 96; }
    else          { Bsrc = Wattn; bias = battn; ldB = 96;  colBase = 0;         nGlobalBase = 192; }

    const int ty = tid >> 4;   // 0..15 (m)
    const int tx = tid & 15;   // 0..15 (n)

    // A-load mapping (2 float4 per thread)
    const int fA0 = tid;             // float4 id
    const int rA0 = fA0 >> 3, kqA0 = fA0 & 7;
    const int fA1 = tid + 256;
    const int rA1 = fA1 >> 3, kqA1 = fA1 & 7;

    float acc[4][6];
    #pragma unroll
    for (int i = 0; i < 4; i++)
        #pragma unroll
        for (int j = 0; j < 6; j++) acc[i][j] = 0.0f;

    float4 avr[2];
    float  bvr[12];

    // ---- prologue: load tile 0 into regs, store to buf 0
    {
        const int k0 = 0;
        avr[0] = *reinterpret_cast<const float4*>(A + (rowBase + rA0) * GK + k0 + kqA0 * 4);
        avr[1] = *reinterpret_cast<const float4*>(A + (rowBase + rA1) * GK + k0 + kqA1 * 4);
        #pragma unroll
        for (int i = 0; i < 12; i++) {
            int e = tid + i * 256;
            int k = e / 96;
            int n = e - k * 96;
            bvr[i] = __ldg(Bsrc + (k0 + k) * ldB + colBase + n);
        }
        As[0][kqA0 * 4 + 0][rA0] = avr[0].x;
        As[0][kqA0 * 4 + 1][rA0] = avr[0].y;
        As[0][kqA0 * 4 + 2][rA0] = avr[0].z;
        As[0][kqA0 * 4 + 3][rA0] = avr[0].w;
        As[0][kqA1 * 4 + 0][rA1] = avr[1].x;
        As[0][kqA1 * 4 + 1][rA1] = avr[1].y;
        As[0][kqA1 * 4 + 2][rA1] = avr[1].z;
        As[0][kqA1 * 4 + 3][rA1] = avr[1].w;
        #pragma unroll
        for (int i = 0; i < 12; i++) {
            int e = tid + i * 256;
            int k = e / 96;
            int n = e - k * 96;
            Bs[0][k][n] = bvr[i];
        }
    }
    __syncthreads();

    const int NT = GK / BK;   // 8 tiles
    for (int t = 0; t < NT; t++) {
        const int cur = t & 1;
        // issue next tile's global loads early (latency hidden by compute)
        if (t + 1 < NT) {
            const int k0 = (t + 1) * BK;
            avr[0] = *reinterpret_cast<const float4*>(A + (rowBase + rA0) * GK + k0 + kqA0 * 4);
            avr[1] = *reinterpret_cast<const float4*>(A + (rowBase + rA1) * GK + k0 + kqA1 * 4);
            #pragma unroll
            for (int i = 0; i < 12; i++) {
                int e = tid + i * 256;
                int k = e / 96;
                int n = e - k * 96;
                bvr[i] = __ldg(Bsrc + (k0 + k) * ldB + colBase + n);
            }
        }

        // compute on current buffer
        #pragma unroll
        for (int k = 0; k < BK; k++) {
            float4 av = *reinterpret_cast<const float4*>(&As[cur][k][ty * 4]);
            float a[4] = {av.x, av.y, av.z, av.w};
            float bv[6];
            float2 b0 = *reinterpret_cast<const float2*>(&Bs[cur][k][tx * 6 + 0]);
            float2 b1 = *reinterpret_cast<const float2*>(&Bs[cur][k][tx * 6 + 2]);
            float2 b2 = *reinterpret_cast<const float2*>(&Bs[cur][k][tx * 6 + 4]);
            bv[0] = b0.x; bv[1] = b0.y; bv[2] = b1.x; bv[3] = b1.y; bv[4] = b2.x; bv[5] = b2.y;
            #pragma unroll
            for (int i = 0; i < 4; i++)
                #pragma unroll
                for (int j = 0; j < 6; j++)
                    acc[i][j] = fmaf(a[i], bv[j], acc[i][j]);
        }

        // store next tile into the other buffer (safe: prior sync drained
        // all reads of that buffer)
        if (t + 1 < NT) {
            const int nxt = 1 - cur;
            As[nxt][kqA0 * 4 + 0][rA0] = avr[0].x;
            As[nxt][kqA0 * 4 + 1][rA0] = avr[0].y;
            As[nxt][kqA0 * 4 + 2][rA0] = avr[0].z;
            As[nxt][kqA0 * 4 + 3][rA0] = avr[0].w;
            As[nxt][kqA1 * 4 + 0][rA1] = avr[1].x;
            As[nxt][kqA1 * 4 + 1][rA1] = avr[1].y;
            As[nxt][kqA1 * 4 + 2][rA1] = avr[1].z;
            As[nxt][kqA1 * 4 + 3][rA1] = avr[1].w;
            #pragma unroll
            for (int i = 0; i < 12; i++) {
                int e = tid + i * 256;
                int k = e / 96;
                int n = e - k * 96;
                Bs[nxt][k][n] = bvr[i];
            }
        }
        __syncthreads();
    }

    // ---- epilogue: add bias, write to g_raw
    #pragma unroll
    for (int i = 0; i < 4; i++) {
        int r = rowBase + ty * 4 + i;
        #pragma unroll
        for (int j = 0; j < 6; j++) {
            int n = tx * 6 + j;
            g_raw[r * NRAW + nGlobalBase + n] = acc[i][j] + __ldg(bias + colBase + n);
        }
    }
}

// ---------------------------------------------------------------------------
// Kernel 2: fused softmax + location transform + bilinear gather + weighted sum
// Block = 256 threads = 4 queries x 64 threads. Each thread handles 4
// contiguous channels (float4). All address math + softmax-scaled bilinear
// weights precomputed ONCE per (query, head, point) into shared memory, so
// the gather loop is just LDS.128 + predicated LDG.128 + FFMA.
// ---------------------------------------------------------------------------
__global__ __launch_bounds__(256) void dfine_sample_kernel(
    const float* __restrict__ refp,   // (32,300,1,4)
    const float* __restrict__ value,  // input_flatten (32, 8400, 256)
    float* __restrict__ out)          // (32,300,256)
{
    __shared__ int   sOffs[4][96][4];  // absolute spatial index (0..8399) or -1
    __shared__ float sWts[4][96][4];   // bilinear weights * softmax weight
    __shared__ float sLog[4][96];      // attn logits -> probabilities

    const int tid  = threadIdx.x;
    const int row0 = blockIdx.x * 4;   // 300 % 4 == 0 -> block never straddles a batch

    // ---- Phase A: per-(query,head,point) address/weight precompute (384 entries)
    #pragma unroll
    for (int e = tid; e < 384; e += 256) {
        int qi = e / 96, j = e % 96;       // j = h*12 + pt
        int row = row0 + qi;
        const float* raw = g_raw + (size_t)row * NRAW;
        float rx = __ldg(refp + row * 4 + 0);
        float ry = __ldg(refp + row * 4 + 1);
        float rw = __ldg(refp + row * 4 + 2);
        float rh = __ldg(refp + row * 4 + 3);
        float ox = raw[2 * j + 0];
        float oy = raw[2 * j + 1];
        sLog[qi][j] = raw[192 + j];

        int pt  = j % 12;
        int lvl = pt >> 2;
        int   W    = (lvl == 0) ? 80 : (lvl == 1) ? 40 : 20;  // H == W
        int   loff = (lvl == 0) ? 0  : (lvl == 1) ? 6400 : 8000;
        float Wf   = (float)W;
        // pscale=1/4, OFFSET_SCALE=0.5 -> 0.125; pixel = loc*W - 0.5
        float ix = (rx + ox * 0.125f * rw) * Wf - 0.5f;
        float iy = (ry + oy * 0.125f * rh) * Wf - 0.5f;
        float fx0 = floorf(ix), fy0 = floorf(iy);
        float fx = ix - fx0, fy = iy - fy0;
        int x0 = (int)fx0, y0 = (int)fy0;
        int x1 = x0 + 1,   y1 = y0 + 1;
        bool vx0 = (unsigned)x0 < (unsigned)W;
        bool vx1 = (unsigned)x1 < (unsigned)W;
        bool vy0 = (unsigned)y0 < (unsigned)W;
        bool vy1 = (unsigned)y1 < (unsigned)W;
        sOffs[qi][j][0] = (vx0 && vy0) ? (loff + y0 * W + x0) : -1;
        sOffs[qi][j][1] = (vx1 && vy0) ? (loff + y0 * W + x1) : -1;
        sOffs[qi][j][2] = (vx0 && vy1) ? (loff + y1 * W + x0) : -1;
        sOffs[qi][j][3] = (vx1 && vy1) ? (loff + y1 * W + x1) : -1;
        float gx = 1.0f - fx, gy = 1.0f - fy;
        sWts[qi][j][0] = gx * gy;
        sWts[qi][j][1] = fx * gy;
        sWts[qi][j][2] = gx * fy;
        sWts[qi][j][3] = fx * fy;
    }
    __syncthreads();

    // ---- Phase B: per-(query,head) softmax over 12 points (in place)
    if (tid < 32) {
        int qi = tid >> 3, h = tid & 7;
        float* L = &sLog[qi][h * 12];
        float m = -1e30f;
        #pragma unroll
        for (int p = 0; p < 12; p++) m = fmaxf(m, L[p]);
        float s = 0.0f;
        #pragma unroll
        for (int p = 0; p < 12; p++) { float ev = expf(L[p] - m); L[p] = ev; s += ev; }
        float inv = 1.0f / s;
        #pragma unroll
        for (int p = 0; p < 12; p++) L[p] *= inv;
    }
    __syncthreads();

    // ---- Phase C: fold softmax weight into bilinear weights
    #pragma unroll
    for (int e = tid; e < 384; e += 256) {
        int qi = e / 96, j = e % 96;
        float w = sLog[qi][j];
        sWts[qi][j][0] *= w;
        sWts[qi][j][1] *= w;
        sWts[qi][j][2] *= w;
        sWts[qi][j][3] *= w;
    }
    __syncthreads();

    // ---- Phase D: gather + accumulate. 64 threads/query, float4 channels.
    const int qi   = tid >> 6;         // query within block
    const int lane = tid & 63;         // channel-quad index 0..63
    const int h    = lane >> 3;        // head (8 channel-quads per head)
    const int row  = row0 + qi;
    const int b    = row / 300;

    // float4 base pointer: channel quad = h*8 + (lane&7)
    const float4* __restrict__ vb =
        (const float4*)value + (size_t)b * 8400 * 64 + h * 8 + (lane & 7);

    float4 acc = make_float4(0.0f, 0.0f, 0.0f, 0.0f);
    #pragma unroll 4
    for (int pt = 0; pt < 12; pt++) {
        int j = h * 12 + pt;
        int4   o = *reinterpret_cast<const int4*>(sOffs[qi][j]);
        float4 w = *reinterpret_cast<const float4*>(sWts[qi][j]);
        if (o.x >= 0) {
            float4 v = __ldg(vb + (size_t)o.x * 64);
            acc.x += w.x * v.x; acc.y += w.x * v.y; acc.z += w.x * v.z; acc.w += w.x * v.w;
        }
        if (o.y >= 0) {
            float4 v = __ldg(vb + (size_t)o.y * 64);
            acc.x += w.y * v.x; acc.y += w.y * v.y; acc.z += w.y * v.z; acc.w += w.y * v.w;
        }
        if (o.z >= 0) {
            float4 v = __ldg(vb + (size_t)o.z * 64);
            acc.x += w.z * v.x; acc.y += w.z * v.y; acc.z += w.z * v.z; acc.w += w.z * v.w;
        }
        if (o.w >= 0) {
            float4 v = __ldg(vb + (size_t)o.w * 64);
            acc.x += w.w * v.x; acc.y += w.w * v.y; acc.z += w.w * v.z; acc.w += w.w * v.w;
        }
    }

    reinterpret_cast<float4*>(out)[(size_t)row * 64 + lane] = acc;
}

// ---------------------------------------------------------------------------
// Launch: inputs in metadata order:
//   0 query (32,300,256) f32        1 reference_points (32,300,1,4) f32
//   2 input_flatten (32,8400,256)   3 W_off (256,192)   4 b_off (192)
//   5 W_attn (256,96)               6 b_attn (96)
// Output: (32,300,256) f32
// ---------------------------------------------------------------------------
extern "C" void kernel_launch(void* const* d_in, const int* in_sizes, int n_in,
                              void* d_out, int out_size) {
    const float* query = (const float*)d_in[0];
    const float* refp  = (const float*)d_in[1];
    const float* value = (const float*)d_in[2];
    const float* Woff  = (const float*)d_in[3];
    const float* boff  = (const float*)d_in[4];
    const float* Wattn = (const float*)d_in[5];
    const float* battn = (const float*)d_in[6];
    float* out = (float*)d_out;

    dim3 ggrid(GM / BM, 3);  // 150 x 3
    dfine_gemm_kernel<<<ggrid, 256>>>(query, Woff, boff, Wattn, battn);
    dfine_sample_kernel<<<GM / 4, 256>>>(refp, value, out);
}